// round 10
// baseline (speedup 1.0000x reference)
#include <cuda_runtime.h>
#include <cuda_bf16.h>

#define NRES 1024
#define CZ   128
#define NB   65
#define GRID 888   // 148 SMs x 6 CTAs (37.3 KB smem each) -> exactly one wave

// out[i][j][c] = W[c][idx(i,j)] + b[c]
// idx(i,j) = 0 if i==j else clamp(round_half_down(r[j]-r[i]), -32, 32) + 32
__global__ __launch_bounds__(256, 4)
void relpos_kernel(const float* __restrict__ r,
                   const float* __restrict__ W,
                   const float* __restrict__ b,
                   float4* __restrict__ out) {
    __shared__ float lut[NB * CZ];   // 33,280 B : lut[k*CZ + c] = W[c][k] + b[c]
    __shared__ float rs[NRES];       //  4,096 B

    const int tid = threadIdx.x;

    // Build LUT once per (persistent) CTA. W row-major [CZ, NB].
    for (int x = tid; x < NB * CZ; x += blockDim.x) {
        int k = x / CZ;
        int c = x - k * CZ;
        lut[x] = W[c * NB + k] + b[c];
    }
    for (int x = tid; x < NRES; x += blockDim.x) rs[x] = r[x];
    __syncthreads();

    const float4* __restrict__ lut4 = (const float4*)lut;     // [NB][32]
    const int v    = tid & 31;   // float4 lane within a row of 128 channels
    const int jsub = tid >> 5;   // warp id -> j offset (8 warps)

    // Persistent loop: each CTA handles rows bid, bid+GRID, ...
    for (int i = blockIdx.x; i < NRES; i += GRID) {
        const float ri = rs[i];
        float4* __restrict__ orow = out + (size_t)i * NRES * (CZ / 4);

        #pragma unroll 4
        for (int j = jsub; j < NRES; j += 8) {
            int idx;
            if (j == i) {
                idx = 0;  // diagonal: all-inf distances -> argmin returns 0
            } else {
                float d  = rs[j] - ri;
                float kf = ceilf(d - 0.5f);            // round-half-down (argmin tie -> lower bin)
                kf = fminf(fmaxf(kf, -32.0f), 32.0f);
                idx = (int)kf + 32;
            }
            // Warp-coalesced 512B streaming store (evict-first: output is never re-read)
            float4 val = lut4[idx * (CZ / 4) + v];
            __stcs(&orow[(size_t)j * (CZ / 4) + v], val);
        }
        // No __syncthreads needed between rows: lut/rs are read-only after init.
    }
}

extern "C" void kernel_launch(void* const* d_in, const int* in_sizes, int n_in,
                              void* d_out, int out_size) {
    const float* r = (const float*)d_in[0];   // residue_index [1024]
    const float* W = (const float*)d_in[1];   // [128, 65]
    const float* b = (const float*)d_in[2];   // [128]
    float4* out = (float4*)d_out;             // [1024, 1024, 128] fp32

    relpos_kernel<<<GRID, 256>>>(r, W, b, out);
}

// round 11
// speedup vs baseline: 1.0829x; 1.0829x over previous
#include <cuda_runtime.h>
#include <cuda_bf16.h>

#define NRES 1024
#define CZ   128
#define NB   65

// Global LUT: lut4[k*32 + v] = float4 of channels {4v..4v+3} for bin k, bias folded in.
__device__ float4 g_lut4[NB * (CZ / 4)];

__global__ void build_lut_kernel(const float* __restrict__ W,
                                 const float* __restrict__ b) {
    int x = blockIdx.x * blockDim.x + threadIdx.x;   // over NB*CZ = 8320
    if (x < NB * CZ) {
        int k = x >> 7;        // x / 128
        int c = x & 127;       // channel
        ((float*)g_lut4)[k * CZ + c] = W[c * NB + k] + b[c];
    }
}

// out[i][j][c] = lut[idx(i,j)][c];  idx = 0 if i==j else clamp(round_half_down(r[j]-r[i]),-32,32)+32
__global__ __launch_bounds__(256, 8)
void relpos_kernel(const float* __restrict__ r,
                   float4* __restrict__ out) {
    __shared__ float rs[NRES];   // 4 KB only -> smem no longer limits occupancy
    const int tid = threadIdx.x;
    for (int x = tid; x < NRES; x += 256) rs[x] = r[x];
    __syncthreads();

    const int i  = blockIdx.x;
    const float ri = rs[i];
    float4* __restrict__ orow = out + (size_t)i * NRES * (CZ / 4);

    const int v    = tid & 31;   // float4 lane within the 128-channel row
    const int jsub = tid >> 5;   // warp id (8 warps) -> j offset

    #pragma unroll 4
    for (int j = jsub; j < NRES; j += 8) {
        int idx;
        if (j == i) {
            idx = 0;  // diagonal: all-inf distances -> argmin returns 0
        } else {
            float d  = rs[j] - ri;
            float kf = ceilf(d - 0.5f);             // round-half-down (argmin tie -> lower bin)
            kf = fminf(fmaxf(kf, -32.0f), 32.0f);
            idx = (int)kf + 32;
        }
        // L1-resident LUT gather (512B warp-coalesced) + 512B coalesced store
        orow[(size_t)j * (CZ / 4) + v] = __ldg(&g_lut4[idx * (CZ / 4) + v]);
    }
}

extern "C" void kernel_launch(void* const* d_in, const int* in_sizes, int n_in,
                              void* d_out, int out_size) {
    const float* r = (const float*)d_in[0];   // residue_index [1024]
    const float* W = (const float*)d_in[1];   // [128, 65]
    const float* b = (const float*)d_in[2];   // [128]
    float4* out = (float4*)d_out;             // [1024, 1024, 128] fp32

    build_lut_kernel<<<(NB * CZ + 255) / 256, 256>>>(W, b);
    relpos_kernel<<<NRES, 256>>>(r, out);
}

// round 15
// speedup vs baseline: 1.1544x; 1.0661x over previous
#include <cuda_runtime.h>
#include <cuda_bf16.h>

#define NRES 1024
#define CZ   128
#define NB   65
#define JSPLIT 2                    // CTAs per row
#define JCHUNK (NRES / JSPLIT)      // 512 j's per CTA

// Global LUT: lut4[k*32 + v] = float4 of channels {4v..4v+3} for bin k, bias folded in.
__device__ float4 g_lut4[NB * (CZ / 4)];

__global__ void build_lut_kernel(const float* __restrict__ W,
                                 const float* __restrict__ b) {
    int x = blockIdx.x * blockDim.x + threadIdx.x;   // over NB*CZ = 8320
    if (x < NB * CZ) {
        int k = x >> 7;        // x / 128
        int c = x & 127;       // channel
        ((float*)g_lut4)[k * CZ + c] = W[c * NB + k] + b[c];
    }
}

// out[i][j][c] = lut[idx(i,j)][c];  idx = 0 if i==j else clamp(round_half_down(r[j]-r[i]),-32,32)+32
__global__ __launch_bounds__(256, 8)
void relpos_kernel(const float* __restrict__ r,
                   float4* __restrict__ out) {
    __shared__ float rs[NRES];   // 4 KB
    const int tid = threadIdx.x;
    for (int x = tid; x < NRES; x += 256) rs[x] = r[x];
    __syncthreads();

    const int i    = blockIdx.x >> 1;          // row
    const int jlo  = (blockIdx.x & 1) * JCHUNK;
    const float ri = rs[i];
    float4* __restrict__ orow = out + (size_t)i * NRES * (CZ / 4);

    const int v    = tid & 31;   // float4 lane within the 128-channel row
    const int jsub = tid >> 5;   // warp id (8 warps) -> j offset

    #pragma unroll 4
    for (int jo = jsub; jo < JCHUNK; jo += 8) {
        const int j = jlo + jo;
        int idx;
        if (j == i) {
            idx = 0;  // diagonal: all-inf distances -> argmin returns 0
        } else {
            float d  = rs[j] - ri;
            float kf = ceilf(d - 0.5f);             // round-half-down (argmin tie -> lower bin)
            kf = fminf(fmaxf(kf, -32.0f), 32.0f);
            idx = (int)kf + 32;
        }
        // L1-resident LUT gather (512B warp-coalesced) + 512B coalesced store
        orow[(size_t)j * (CZ / 4) + v] = __ldg(&g_lut4[idx * (CZ / 4) + v]);
    }
}

extern "C" void kernel_launch(void* const* d_in, const int* in_sizes, int n_in,
                              void* d_out, int out_size) {
    const float* r = (const float*)d_in[0];   // residue_index [1024]
    const float* W = (const float*)d_in[1];   // [128, 65]
    const float* b = (const float*)d_in[2];   // [128]
    float4* out = (float4*)d_out;             // [1024, 1024, 128] fp32

    build_lut_kernel<<<(NB * CZ + 255) / 256, 256>>>(W, b);
    relpos_kernel<<<NRES * JSPLIT, 256>>>(r, out);
}

// round 17
// speedup vs baseline: 1.2470x; 1.0802x over previous
#include <cuda_runtime.h>
#include <cuda_bf16.h>

#define NRES 1024
#define CZ   128
#define NB   65
#define JSPLIT 8                    // CTAs per row (fine-grained for wave smoothing)
#define JCHUNK (NRES / JSPLIT)      // 128 j's per CTA

// Global LUT: lut4[k*32 + v] = float4 of channels {4v..4v+3} for bin k, bias folded in.
__device__ float4 g_lut4[NB * (CZ / 4)];

__global__ void build_lut_kernel(const float* __restrict__ W,
                                 const float* __restrict__ b) {
    int x = blockIdx.x * blockDim.x + threadIdx.x;   // over NB*CZ = 8320
    if (x < NB * CZ) {
        int k = x >> 7;        // x / 128
        int c = x & 127;       // channel
        ((float*)g_lut4)[k * CZ + c] = W[c * NB + k] + b[c];
    }
}

// out[i][j][c] = lut[idx(i,j)][c];  idx = 0 if i==j else clamp(round_half_down(r[j]-r[i]),-32,32)+32
__global__ __launch_bounds__(256, 8)
void relpos_kernel(const float* __restrict__ r,
                   float4* __restrict__ out) {
    __shared__ float rs[NRES];   // 4 KB
    const int tid = threadIdx.x;
    for (int x = tid; x < NRES; x += 256) rs[x] = r[x];
    __syncthreads();

    const int i    = blockIdx.x >> 3;                 // row
    const int jlo  = (blockIdx.x & 7) * JCHUNK;       // 128-wide j window
    const float ri = rs[i];
    float4* __restrict__ orow = out + (size_t)i * NRES * (CZ / 4);

    const int v    = tid & 31;   // float4 lane within the 128-channel row
    const int jsub = tid >> 5;   // warp id (8 warps) -> j offset

    #pragma unroll 4
    for (int jo = jsub; jo < JCHUNK; jo += 8) {
        const int j = jlo + jo;
        int idx;
        if (j == i) {
            idx = 0;  // diagonal: all-inf distances -> argmin returns 0
        } else {
            float d  = rs[j] - ri;
            float kf = ceilf(d - 0.5f);             // round-half-down (argmin tie -> lower bin)
            kf = fminf(fmaxf(kf, -32.0f), 32.0f);
            idx = (int)kf + 32;
        }
        // L1-resident LUT gather (512B warp-coalesced) + 512B coalesced store
        orow[(size_t)j * (CZ / 4) + v] = __ldg(&g_lut4[idx * (CZ / 4) + v]);
    }
}

extern "C" void kernel_launch(void* const* d_in, const int* in_sizes, int n_in,
                              void* d_out, int out_size) {
    const float* r = (const float*)d_in[0];   // residue_index [1024]
    const float* W = (const float*)d_in[1];   // [128, 65]
    const float* b = (const float*)d_in[2];   // [128]
    float4* out = (float4*)d_out;             // [1024, 1024, 128] fp32

    build_lut_kernel<<<(NB * CZ + 255) / 256, 256>>>(W, b);
    relpos_kernel<<<NRES * JSPLIT, 256>>>(r, out);
}